// round 16
// baseline (speedup 1.0000x reference)
#include <cuda_runtime.h>
#include <math.h>

// ---------------------------------------------------------------------------
// BiGRU encoder. B=32, T=1024, N=512.
// Phase 1: gi[dir][t][b][3N] = x_slice @ Wih^T + bih  (parallel GEMM, f32x2)
// Phase 2: persistent kernel, 64 CTAs/direction, flag grid-barrier per step.
// ---------------------------------------------------------------------------

__device__ float g_gi[2ull * 32768ull * 1536ull];   // [dir][t*32+b][3N]
__device__ float g_h[2 * 2 * 512 * 32];             // [dir][parity][k][b]
__device__ unsigned g_flag[2][64];                  // per-CTA step flags

union F2 { float2 f; unsigned long long u; };

__device__ __forceinline__ void fma2(F2& d, F2 a, F2 b) {
    asm("fma.rn.f32x2 %0, %1, %2, %0;" : "+l"(d.u) : "l"(a.u), "l"(b.u));
}
__device__ __forceinline__ void add2(F2& d, F2 a) {
    asm("add.rn.f32x2 %0, %0, %1;" : "+l"(d.u) : "l"(a.u));
}
__device__ __forceinline__ F2 splat2(float v) { F2 r; r.f = make_float2(v, v); return r; }

__device__ __forceinline__ float fsig(float v) { return 1.0f / (1.0f + __expf(-v)); }
__device__ __forceinline__ float ftanh(float v) {
    float a = fabsf(v);
    float e = __expf(-2.0f * a);
    float t = (1.0f - e) / (1.0f + e);
    return copysignf(t, v);
}

// ---------------------------------------------------------------------------
// Phase 1 GEMM: C[m][j] = sum_k A[m][k] * W[j][k] + bih[j]
//   m = t*32 + b, A[m][k] = x[b][tt][k], tt = dir ? 1023-t : t
// BM=BN=128, BK=16, 256 threads, 8x8 thread tile via f32x2.
// Also resets g_h (parity buffers) and g_flag for the recurrent phase.
// ---------------------------------------------------------------------------
__global__ void __launch_bounds__(256) gi_gemm(
    const float* __restrict__ x,
    const float* __restrict__ WihF, const float* __restrict__ WihB,
    const float* __restrict__ bihF, const float* __restrict__ bihB)
{
    __shared__ float As[16][128];
    __shared__ float Bs[16][128];

    const int d   = blockIdx.z;
    const float* __restrict__ W   = d ? WihB : WihF;
    const float* __restrict__ bih = d ? bihB : bihF;
    const int j0  = blockIdx.x * 128;
    const int m0  = blockIdx.y * 128;
    const int tid = threadIdx.x;

    // fold state init into the first row of gemm CTAs (completes before
    // `recurrent` launches, by stream ordering)
    if (blockIdx.z == 0 && blockIdx.y == 0) {
        int g = blockIdx.x * 256 + tid;              // 3072 threads
        for (int i = g; i < 16384; i += 3072)
            ((float4*)g_h)[i] = make_float4(0.f, 0.f, 0.f, 0.f);
        if (g < 128) ((unsigned*)g_flag)[g] = 0u;
    }

    int rowA[2], kqA[2];
    const float* aptr[2];
    const float* bptr[2];
    #pragma unroll
    for (int h = 0; h < 2; ++h) {
        int idx = tid + 256 * h;
        int row = idx >> 2, kq = idx & 3;
        rowA[h] = row; kqA[h] = kq;
        int m = m0 + row;
        int b = m & 31, t = m >> 5;
        int tt = d ? (1023 - t) : t;
        aptr[h] = x + ((size_t)b * 1024 + tt) * 512 + kq * 4;
        bptr[h] = W + (size_t)(j0 + row) * 512 + kq * 4;
    }
    const int ty = tid >> 4, tx = tid & 15;

    F2 c[8][4];
    #pragma unroll
    for (int r = 0; r < 8; ++r)
        #pragma unroll
        for (int q = 0; q < 4; ++q) c[r][q].f = make_float2(0.f, 0.f);

    float4 pa[2], pb[2];
    #pragma unroll
    for (int h = 0; h < 2; ++h) {
        pa[h] = *(const float4*)(aptr[h]);
        pb[h] = *(const float4*)(bptr[h]);
    }

    for (int kt = 0; kt < 32; ++kt) {
        __syncthreads();
        #pragma unroll
        for (int h = 0; h < 2; ++h) {
            int kk = kqA[h] * 4, rw = rowA[h];
            As[kk + 0][rw] = pa[h].x; As[kk + 1][rw] = pa[h].y;
            As[kk + 2][rw] = pa[h].z; As[kk + 3][rw] = pa[h].w;
            Bs[kk + 0][rw] = pb[h].x; Bs[kk + 1][rw] = pb[h].y;
            Bs[kk + 2][rw] = pb[h].z; Bs[kk + 3][rw] = pb[h].w;
        }
        __syncthreads();
        if (kt < 31) {
            #pragma unroll
            for (int h = 0; h < 2; ++h) {
                pa[h] = *(const float4*)(aptr[h] + (kt + 1) * 16);
                pb[h] = *(const float4*)(bptr[h] + (kt + 1) * 16);
            }
        }
        #pragma unroll
        for (int kk = 0; kk < 16; ++kk) {
            float4 alo = *(const float4*)&As[kk][ty * 4];
            float4 ahi = *(const float4*)&As[kk][64 + ty * 4];
            float4 blo = *(const float4*)&Bs[kk][tx * 4];
            float4 bhi = *(const float4*)&Bs[kk][64 + tx * 4];
            float av[8] = {alo.x, alo.y, alo.z, alo.w, ahi.x, ahi.y, ahi.z, ahi.w};
            F2 bv[4];
            bv[0].f = make_float2(blo.x, blo.y); bv[1].f = make_float2(blo.z, blo.w);
            bv[2].f = make_float2(bhi.x, bhi.y); bv[3].f = make_float2(bhi.z, bhi.w);
            #pragma unroll
            for (int r = 0; r < 8; ++r) {
                F2 a2 = splat2(av[r]);
                #pragma unroll
                for (int q = 0; q < 4; ++q) fma2(c[r][q], a2, bv[q]);
            }
        }
    }

    int cols[4] = { j0 + tx * 4, j0 + tx * 4 + 2, j0 + 64 + tx * 4, j0 + 64 + tx * 4 + 2 };
    float2 bias[4];
    #pragma unroll
    for (int q = 0; q < 4; ++q) bias[q] = *(const float2*)(bih + cols[q]);

    #pragma unroll
    for (int r = 0; r < 8; ++r) {
        int m = m0 + ((r < 4) ? (ty * 4 + r) : (64 + ty * 4 + (r - 4)));
        float* orow = g_gi + ((size_t)(d * 32768 + m)) * 1536;
        #pragma unroll
        for (int q = 0; q < 4; ++q) {
            float2 v = c[r][q].f;
            v.x += bias[q].x; v.y += bias[q].y;
            *(float2*)(orow + cols[q]) = v;
        }
    }
}

// ---------------------------------------------------------------------------
// In-place pair-compacting butterfly reduce over 32 batch partials held as
// F2 a[16] (a[p] = batches {2p, 2p+1}). 64-bit shuffles + add.rn.f32x2:
// 15 shfl64 + 1 shfl32 per reduce (vs 93 shfl32 naive). Lane l ends with the
// full sum for batch l.
// ---------------------------------------------------------------------------
template<int M>   // M in {16,8,4,2}: distance M in batch space = M/2 pairs
__device__ __forceinline__ void pstage(F2* a, int lane) {
    #pragma unroll
    for (int i = 0; i < M / 2; ++i) {
        F2 mine  = (lane & M) ? a[i + M / 2] : a[i];
        F2 other = (lane & M) ? a[i]         : a[i + M / 2];
        F2 recv; recv.u = __shfl_xor_sync(0xffffffffu, other.u, M);
        add2(mine, recv);
        a[i] = mine;
    }
}
__device__ __forceinline__ float preduce(F2* a, int lane) {
    pstage<16>(a, lane); pstage<8>(a, lane); pstage<4>(a, lane); pstage<2>(a, lane);
    float mine  = (lane & 1) ? a[0].f.y : a[0].f.x;
    float other = (lane & 1) ? a[0].f.x : a[0].f.y;
    float recv  = __shfl_xor_sync(0xffffffffu, other, 1);
    return mine + recv;
}

// ---------------------------------------------------------------------------
// Phase 2: persistent recurrent kernel. 128 CTAs (dir = blockIdx.x>>6).
// Warp w of CTA c owns hidden column i = c*8+w; Whh rows live in registers.
// h_s layout: [k][b] row stride 34 floats (conflict-free LDS.64 pairs).
// Grid barrier: per-CTA flags, 64 spinner threads, fence-cumulativity pattern.
// ---------------------------------------------------------------------------
__global__ void __launch_bounds__(256, 1) recurrent(
    const float* __restrict__ x,
    const float* __restrict__ WhhF, const float* __restrict__ WhhB,
    const float* __restrict__ bhhF, const float* __restrict__ bhhB,
    float* __restrict__ out)
{
    extern __shared__ float h_s[];          // 512*34 floats + 288 out-stage
    float* ostage = h_s + 512 * 34;         // [b][col] stride 9

    const int d     = blockIdx.x >> 6;
    const int c     = blockIdx.x & 63;
    const int tid   = threadIdx.x;
    const int w     = tid >> 5, lane = tid & 31;
    const int i_col = c * 8 + w;

    const float* __restrict__ Whh = d ? WhhB : WhhF;
    const float* __restrict__ bhh = d ? bhhB : bhhF;

    float Wr[16], Wz[16], Wn[16];
    #pragma unroll
    for (int j = 0; j < 16; ++j) {
        int k = lane + 32 * j;
        Wr[j] = Whh[(size_t)(0 * 512 + i_col) * 512 + k];
        Wz[j] = Whh[(size_t)(1 * 512 + i_col) * 512 + k];
        Wn[j] = Whh[(size_t)(2 * 512 + i_col) * 512 + k];
    }
    const float bhr = bhh[i_col], bhz = bhh[512 + i_col], bhn = bhh[1024 + i_col];

    const float* __restrict__ gi_base = g_gi + (size_t)d * 32768 * 1536;

    for (int t = 0; t < 1024; ++t) {
        // --- broadcast h (64KB) from L2 (k-major) into smem [k][b], stride 34
        const float4* __restrict__ hg = (const float4*)(g_h + ((d * 2 + (t & 1)) << 14));
        #pragma unroll
        for (int u = 0; u < 16; ++u) {
            int v = tid + 256 * u;
            float4 hv = __ldcg(hg + v);
            int k = v >> 3, b0 = (v & 7) * 4;
            float2* dst = (float2*)(h_s + k * 34 + b0);
            dst[0] = make_float2(hv.x, hv.y);
            dst[1] = make_float2(hv.z, hv.w);
        }
        // --- prefetch epilogue operands (b = lane, i = i_col)
        const float* gp = gi_base + ((size_t)(t * 32 + lane)) * 1536 + i_col;
        float gir = __ldg(gp), giz = __ldg(gp + 512), gin = __ldg(gp + 1024);
        int tt = d ? (1023 - t) : t;
        float xv = __ldg(x + ((size_t)lane * 1024 + tt) * 512 + i_col);
        __syncthreads();

        // --- MAC: gh[g][b] = sum_k Whh[g][i_col][k] * h[b][k]
        F2 ar[16], az[16], an[16];
        #pragma unroll
        for (int bp = 0; bp < 16; ++bp) {
            ar[bp].f = make_float2(0.f, 0.f);
            az[bp].f = make_float2(0.f, 0.f);
            an[bp].f = make_float2(0.f, 0.f);
        }
        #pragma unroll
        for (int j = 0; j < 16; ++j) {
            const float2* hp = (const float2*)(h_s + (lane + 32 * j) * 34);
            F2 wr2 = splat2(Wr[j]), wz2 = splat2(Wz[j]), wn2 = splat2(Wn[j]);
            #pragma unroll
            for (int bp = 0; bp < 16; ++bp) {
                F2 hv; hv.f = hp[bp];
                fma2(ar[bp], wr2, hv);
                fma2(az[bp], wz2, hv);
                fma2(an[bp], wn2, hv);
            }
        }

        // --- in-place pair reduce; lane l ends with totals for batch l
        float ghr = preduce(ar, lane);
        float ghz = preduce(az, lane);
        float ghn = preduce(an, lane);

        // --- gates for (b = lane, i = i_col)
        float r  = fsig(gir + ghr + bhr);
        float z  = fsig(giz + ghz + bhz);
        float nn = ftanh(gin + r * (ghn + bhn));
        float hold = h_s[i_col * 34 + lane];
        float hnew = (1.0f - z) * nn + z * hold;

        float* hw = g_h + ((d * 2 + ((t & 1) ^ 1)) << 14);
        __stcg(hw + i_col * 32 + lane, hnew);
        ostage[lane * 9 + w] = hnew + xv;           // stage for coalesced out

        __syncthreads();                            // h stores + ostage done

        // --- coalesced out write: 8 consecutive cols per batch row (32B segs)
        {
            int b = tid >> 3, cc = tid & 7;
            out[((size_t)b * 1024 + t) * 1024 + d * 512 + c * 8 + cc] =
                ostage[b * 9 + cc];
        }

        // --- distributed-flag grid barrier across this direction's 64 CTAs
        if (tid == 0) {
            __threadfence();                        // release h stores (cumulative)
            *(volatile unsigned*)&g_flag[d][c] = (unsigned)(t + 1);
        }
        if (tid < 64) {
            volatile unsigned* f = &g_flag[d][tid];
            while (*f < (unsigned)(t + 1)) { }
            __threadfence();                        // acquire peers' h stores
        }
        __syncthreads();
    }
}

// ---------------------------------------------------------------------------
extern "C" void kernel_launch(void* const* d_in, const int* in_sizes, int n_in,
                              void* d_out, int out_size) {
    const float* x    = (const float*)d_in[0];
    const float* WihF = (const float*)d_in[1];
    const float* WhhF = (const float*)d_in[2];
    const float* bihF = (const float*)d_in[3];
    const float* bhhF = (const float*)d_in[4];
    const float* WihB = (const float*)d_in[5];
    const float* WhhB = (const float*)d_in[6];
    const float* bihB = (const float*)d_in[7];
    const float* bhhB = (const float*)d_in[8];
    float* out = (float*)d_out;

    static int smem_set = 0;
    if (!smem_set) {
        cudaFuncSetAttribute(recurrent, cudaFuncAttributeMaxDynamicSharedMemorySize,
                             (512 * 34 + 32 * 9) * 4);
        smem_set = 1;
    }

    gi_gemm<<<dim3(12, 256, 2), 256>>>(x, WihF, WihB, bihF, bihB);
    recurrent<<<128, 256, (512 * 34 + 32 * 9) * 4>>>(x, WhhF, WhhB, bhhF, bhhB, out);
}

// round 17
// speedup vs baseline: 1.4629x; 1.4629x over previous
#include <cuda_runtime.h>
#include <math.h>

// ---------------------------------------------------------------------------
// BiGRU encoder. B=32, T=1024, N=512.
// Phase 1: gi[dir][t][b][3N] = x_slice @ Wih^T + bih  (parallel GEMM, f32x2)
// Phase 2: persistent kernel, 64 CTAs/direction, central atomic grid barrier.
// ---------------------------------------------------------------------------

__device__ float g_gi[2ull * 32768ull * 1536ull];   // [dir][t*32+b][3N]
__device__ float g_h[2 * 2 * 512 * 32];             // [dir][parity][k][b]
__device__ unsigned g_count[2];
__device__ unsigned g_release[2];

union F2 { float2 f; unsigned long long u; };

__device__ __forceinline__ void fma2(F2& d, F2 a, F2 b) {
    asm("fma.rn.f32x2 %0, %1, %2, %0;" : "+l"(d.u) : "l"(a.u), "l"(b.u));
}
__device__ __forceinline__ void add2(F2& d, F2 a) {
    asm("add.rn.f32x2 %0, %0, %1;" : "+l"(d.u) : "l"(a.u));
}
__device__ __forceinline__ F2 splat2(float v) { F2 r; r.f = make_float2(v, v); return r; }

__device__ __forceinline__ float fsig(float v) { return 1.0f / (1.0f + __expf(-v)); }
__device__ __forceinline__ float ftanh(float v) {
    float a = fabsf(v);
    float e = __expf(-2.0f * a);
    float t = (1.0f - e) / (1.0f + e);
    return copysignf(t, v);
}

// ---------------------------------------------------------------------------
// Phase 1 GEMM: C[m][j] = sum_k A[m][k] * W[j][k] + bih[j]
//   m = t*32 + b, A[m][k] = x[b][tt][k], tt = dir ? 1023-t : t
// BM=BN=128, BK=16, 256 threads, 8x8 thread tile via f32x2.
// Also resets g_h / barrier counters for the recurrent phase (stream-ordered).
// ---------------------------------------------------------------------------
__global__ void __launch_bounds__(256) gi_gemm(
    const float* __restrict__ x,
    const float* __restrict__ WihF, const float* __restrict__ WihB,
    const float* __restrict__ bihF, const float* __restrict__ bihB)
{
    __shared__ float As[16][128];
    __shared__ float Bs[16][128];

    const int d   = blockIdx.z;
    const float* __restrict__ W   = d ? WihB : WihF;
    const float* __restrict__ bih = d ? bihB : bihF;
    const int j0  = blockIdx.x * 128;
    const int m0  = blockIdx.y * 128;
    const int tid = threadIdx.x;

    // fold state init into the first row of gemm CTAs
    if (blockIdx.z == 0 && blockIdx.y == 0) {
        int g = blockIdx.x * 256 + tid;              // 3072 threads
        for (int i = g; i < 16384; i += 3072)
            ((float4*)g_h)[i] = make_float4(0.f, 0.f, 0.f, 0.f);
        if (g < 2) { g_count[g] = 0u; g_release[g] = 0u; }
    }

    int rowA[2], kqA[2];
    const float* aptr[2];
    const float* bptr[2];
    #pragma unroll
    for (int h = 0; h < 2; ++h) {
        int idx = tid + 256 * h;
        int row = idx >> 2, kq = idx & 3;
        rowA[h] = row; kqA[h] = kq;
        int m = m0 + row;
        int b = m & 31, t = m >> 5;
        int tt = d ? (1023 - t) : t;
        aptr[h] = x + ((size_t)b * 1024 + tt) * 512 + kq * 4;
        bptr[h] = W + (size_t)(j0 + row) * 512 + kq * 4;
    }
    const int ty = tid >> 4, tx = tid & 15;

    F2 c[8][4];
    #pragma unroll
    for (int r = 0; r < 8; ++r)
        #pragma unroll
        for (int q = 0; q < 4; ++q) c[r][q].f = make_float2(0.f, 0.f);

    float4 pa[2], pb[2];
    #pragma unroll
    for (int h = 0; h < 2; ++h) {
        pa[h] = *(const float4*)(aptr[h]);
        pb[h] = *(const float4*)(bptr[h]);
    }

    for (int kt = 0; kt < 32; ++kt) {
        __syncthreads();
        #pragma unroll
        for (int h = 0; h < 2; ++h) {
            int kk = kqA[h] * 4, rw = rowA[h];
            As[kk + 0][rw] = pa[h].x; As[kk + 1][rw] = pa[h].y;
            As[kk + 2][rw] = pa[h].z; As[kk + 3][rw] = pa[h].w;
            Bs[kk + 0][rw] = pb[h].x; Bs[kk + 1][rw] = pb[h].y;
            Bs[kk + 2][rw] = pb[h].z; Bs[kk + 3][rw] = pb[h].w;
        }
        __syncthreads();
        if (kt < 31) {
            #pragma unroll
            for (int h = 0; h < 2; ++h) {
                pa[h] = *(const float4*)(aptr[h] + (kt + 1) * 16);
                pb[h] = *(const float4*)(bptr[h] + (kt + 1) * 16);
            }
        }
        #pragma unroll
        for (int kk = 0; kk < 16; ++kk) {
            float4 alo = *(const float4*)&As[kk][ty * 4];
            float4 ahi = *(const float4*)&As[kk][64 + ty * 4];
            float4 blo = *(const float4*)&Bs[kk][tx * 4];
            float4 bhi = *(const float4*)&Bs[kk][64 + tx * 4];
            float av[8] = {alo.x, alo.y, alo.z, alo.w, ahi.x, ahi.y, ahi.z, ahi.w};
            F2 bv[4];
            bv[0].f = make_float2(blo.x, blo.y); bv[1].f = make_float2(blo.z, blo.w);
            bv[2].f = make_float2(bhi.x, bhi.y); bv[3].f = make_float2(bhi.z, bhi.w);
            #pragma unroll
            for (int r = 0; r < 8; ++r) {
                F2 a2 = splat2(av[r]);
                #pragma unroll
                for (int q = 0; q < 4; ++q) fma2(c[r][q], a2, bv[q]);
            }
        }
    }

    int cols[4] = { j0 + tx * 4, j0 + tx * 4 + 2, j0 + 64 + tx * 4, j0 + 64 + tx * 4 + 2 };
    float2 bias[4];
    #pragma unroll
    for (int q = 0; q < 4; ++q) bias[q] = *(const float2*)(bih + cols[q]);

    #pragma unroll
    for (int r = 0; r < 8; ++r) {
        int m = m0 + ((r < 4) ? (ty * 4 + r) : (64 + ty * 4 + (r - 4)));
        float* orow = g_gi + ((size_t)(d * 32768 + m)) * 1536;
        #pragma unroll
        for (int q = 0; q < 4; ++q) {
            float2 v = c[r][q].f;
            v.x += bias[q].x; v.y += bias[q].y;
            *(float2*)(orow + cols[q]) = v;
        }
    }
}

// ---------------------------------------------------------------------------
// In-place pair-compacting butterfly reduce over 32 batch partials held as
// F2 a[16] (a[p] = batches {2p, 2p+1}). Lane l ends with the full sum for
// batch l. 15 shfl64 + 1 shfl32 per reduce, zero extra registers.
// ---------------------------------------------------------------------------
template<int M>   // M in {16,8,4,2}: distance M in batch space = M/2 pairs
__device__ __forceinline__ void pstage(F2* a, int lane) {
    #pragma unroll
    for (int i = 0; i < M / 2; ++i) {
        F2 mine  = (lane & M) ? a[i + M / 2] : a[i];
        F2 other = (lane & M) ? a[i]         : a[i + M / 2];
        F2 recv; recv.u = __shfl_xor_sync(0xffffffffu, other.u, M);
        add2(mine, recv);
        a[i] = mine;
    }
}
__device__ __forceinline__ float preduce(F2* a, int lane) {
    pstage<16>(a, lane); pstage<8>(a, lane); pstage<4>(a, lane); pstage<2>(a, lane);
    float mine  = (lane & 1) ? a[0].f.y : a[0].f.x;
    float other = (lane & 1) ? a[0].f.x : a[0].f.y;
    float recv  = __shfl_xor_sync(0xffffffffu, other, 1);
    return mine + recv;
}

// ---------------------------------------------------------------------------
// Phase 2: persistent recurrent kernel. 128 CTAs (dir = blockIdx.x>>6).
// Warp w of CTA c owns hidden column i = c*8+w; Whh rows live in registers.
// h_s layout: [k][b] row stride 34 floats (conflict-free LDS.64 pairs).
// Central atomic barrier; out stores issued AFTER the fence/arrive so the
// fence only drains the single coalesced h line per warp.
// ---------------------------------------------------------------------------
__global__ void __launch_bounds__(256, 1) recurrent(
    const float* __restrict__ x,
    const float* __restrict__ WhhF, const float* __restrict__ WhhB,
    const float* __restrict__ bhhF, const float* __restrict__ bhhB,
    float* __restrict__ out)
{
    extern __shared__ float h_s[];   // 512 * 34 floats

    const int d     = blockIdx.x >> 6;
    const int c     = blockIdx.x & 63;
    const int tid   = threadIdx.x;
    const int w     = tid >> 5, lane = tid & 31;
    const int i_col = c * 8 + w;

    const float* __restrict__ Whh = d ? WhhB : WhhF;
    const float* __restrict__ bhh = d ? bhhB : bhhF;

    float Wr[16], Wz[16], Wn[16];
    #pragma unroll
    for (int j = 0; j < 16; ++j) {
        int k = lane + 32 * j;
        Wr[j] = Whh[(size_t)(0 * 512 + i_col) * 512 + k];
        Wz[j] = Whh[(size_t)(1 * 512 + i_col) * 512 + k];
        Wn[j] = Whh[(size_t)(2 * 512 + i_col) * 512 + k];
    }
    const float bhr = bhh[i_col], bhz = bhh[512 + i_col], bhn = bhh[1024 + i_col];

    const float* __restrict__ gi_base = g_gi + (size_t)d * 32768 * 1536;

    for (int t = 0; t < 1024; ++t) {
        // --- broadcast h (64KB) from L2 (k-major) into smem [k][b], stride 34
        const float4* __restrict__ hg = (const float4*)(g_h + ((d * 2 + (t & 1)) << 14));
        #pragma unroll
        for (int u = 0; u < 16; ++u) {
            int v = tid + 256 * u;
            float4 hv = __ldcg(hg + v);
            int k = v >> 3, b0 = (v & 7) * 4;
            float2* dst = (float2*)(h_s + k * 34 + b0);
            dst[0] = make_float2(hv.x, hv.y);
            dst[1] = make_float2(hv.z, hv.w);
        }
        // --- prefetch epilogue operands (b = lane, i = i_col)
        const float* gp = gi_base + ((size_t)(t * 32 + lane)) * 1536 + i_col;
        float gir = __ldg(gp), giz = __ldg(gp + 512), gin = __ldg(gp + 1024);
        int tt = d ? (1023 - t) : t;
        float xv = __ldg(x + ((size_t)lane * 1024 + tt) * 512 + i_col);
        __syncthreads();

        // --- MAC: gh[g][b] = sum_k Whh[g][i_col][k] * h[b][k]
        F2 ar[16], az[16], an[16];
        #pragma unroll
        for (int bp = 0; bp < 16; ++bp) {
            ar[bp].f = make_float2(0.f, 0.f);
            az[bp].f = make_float2(0.f, 0.f);
            an[bp].f = make_float2(0.f, 0.f);
        }
        #pragma unroll
        for (int j = 0; j < 16; ++j) {
            const float2* hp = (const float2*)(h_s + (lane + 32 * j) * 34);
            F2 wr2 = splat2(Wr[j]), wz2 = splat2(Wz[j]), wn2 = splat2(Wn[j]);
            #pragma unroll
            for (int bp = 0; bp < 16; ++bp) {
                F2 hv; hv.f = hp[bp];
                fma2(ar[bp], wr2, hv);
                fma2(az[bp], wz2, hv);
                fma2(an[bp], wn2, hv);
            }
        }

        // --- in-place pair reduce; lane l ends with totals for batch l
        float ghr = preduce(ar, lane);
        float ghz = preduce(az, lane);
        float ghn = preduce(an, lane);

        // --- gates for (b = lane, i = i_col)
        float r  = fsig(gir + ghr + bhr);
        float z  = fsig(giz + ghz + bhz);
        float nn = ftanh(gin + r * (ghn + bhn));
        float hold = h_s[i_col * 34 + lane];
        float hnew = (1.0f - z) * nn + z * hold;

        // --- h store (1 coalesced 128B line per warp), then barrier arrive.
        float* hw = g_h + ((d * 2 + ((t & 1) ^ 1)) << 14);
        __stcg(hw + i_col * 32 + lane, hnew);

        __syncthreads();              // all warps' h stores issued

        unsigned arr = 64u;           // sentinel for non-tid0
        if (tid == 0) {
            __threadfence();          // drains only h stores (cumulative over CTA)
            arr = atomicAdd(&g_count[d], 1u);
            if (arr == 63u) {
                atomicExch(&g_count[d], 0u);
                __threadfence();
                atomicAdd(&g_release[d], 1u);
            }
        }

        // --- out write happens in the poll window, off the barrier path
        out[((size_t)lane * 1024 + t) * 1024 + d * 512 + i_col] = hnew + xv;

        if (tid == 0 && arr != 63u) {
            volatile unsigned* rel = &g_release[d];
            unsigned tgt = (unsigned)(t + 1);
            while (*rel < tgt) { }
            __threadfence();
        }
        __syncthreads();
    }
}

// ---------------------------------------------------------------------------
extern "C" void kernel_launch(void* const* d_in, const int* in_sizes, int n_in,
                              void* d_out, int out_size) {
    const float* x    = (const float*)d_in[0];
    const float* WihF = (const float*)d_in[1];
    const float* WhhF = (const float*)d_in[2];
    const float* bihF = (const float*)d_in[3];
    const float* bhhF = (const float*)d_in[4];
    const float* WihB = (const float*)d_in[5];
    const float* WhhB = (const float*)d_in[6];
    const float* bihB = (const float*)d_in[7];
    const float* bhhB = (const float*)d_in[8];
    float* out = (float*)d_out;

    cudaFuncSetAttribute(recurrent, cudaFuncAttributeMaxDynamicSharedMemorySize,
                         512 * 34 * 4);

    gi_gemm<<<dim3(12, 256, 2), 256>>>(x, WihF, WihB, bihF, bihB);
    recurrent<<<128, 256, 512 * 34 * 4>>>(x, WhhF, WhhB, bhhF, bhhB, out);
}